// round 3
// baseline (speedup 1.0000x reference)
#include <cuda_runtime.h>

// Binarization_69930657513784: adaptive 2-order residual sign binarization
// x: (4096, 11008) fp32, mask: (4096, 11008) bool stored as INT32
// -> out: (4096, 11008) fp32
//
// One CTA per row. Row (2752 float4) cached in registers across 1024 threads
// (3 float4 each); mask cached as 12 packed bits per thread. Order-2 stats
// derived analytically from order-1 stats => exactly ONE global read of
// x/mask and ONE global write of out. HBM-bound, ~541 MB total traffic.

constexpr int IC      = 11008;
constexpr int VECS    = IC / 4;                         // 2752
constexpr int THREADS = 1024;
constexpr int KMAX    = (VECS + THREADS - 1) / THREADS; // 3
#define SQRT_2_OVER_PI 0.7978845608028654f

__device__ __forceinline__ float fsign(float c) {
    return (c > 0.0f) ? 1.0f : ((c < 0.0f) ? -1.0f : 0.0f);
}

// Block-wide sum reduction of N values. 32 warps exactly (1024 threads).
template <int N>
__device__ __forceinline__ void block_reduce(float (&vals)[N], float* sred, int tid) {
    const int lane = tid & 31;
    const int warp = tid >> 5;
#pragma unroll
    for (int n = 0; n < N; ++n) {
#pragma unroll
        for (int o = 16; o > 0; o >>= 1)
            vals[n] += __shfl_xor_sync(0xffffffffu, vals[n], o);
    }
    if (lane == 0) {
#pragma unroll
        for (int n = 0; n < N; ++n) sred[warp * N + n] = vals[n];
    }
    __syncthreads();
    if (warp == 0) {
#pragma unroll
        for (int n = 0; n < N; ++n) vals[n] = sred[lane * N + n];
#pragma unroll
        for (int n = 0; n < N; ++n) {
#pragma unroll
            for (int o = 16; o > 0; o >>= 1)
                vals[n] += __shfl_xor_sync(0xffffffffu, vals[n], o);
        }
        if (lane == 0) {
#pragma unroll
            for (int n = 0; n < N; ++n) sred[n] = vals[n];
        }
    }
    __syncthreads();
#pragma unroll
    for (int n = 0; n < N; ++n) vals[n] = sred[n];
    __syncthreads();  // protect sred for reuse by the next reduction
}

__global__ __launch_bounds__(THREADS, 1)
void binarize_kernel(const float* __restrict__ x,
                     const int* __restrict__ mask,
                     float* __restrict__ out)
{
    __shared__ float sred[32 * 5];
    const int tid  = threadIdx.x;
    const size_t base = (size_t)blockIdx.x * IC;
    const float4* xr   = reinterpret_cast<const float4*>(x + base);
    const int4*   mr   = reinterpret_cast<const int4*>(mask + base);
    float4*       outr = reinterpret_cast<float4*>(out + base);

    // Register-cached row slice: masked values + packed mask bits.
    float        v[KMAX][4];
    unsigned int mbits = 0;   // bit (k*4+j) = mask of element (k, j)

    // ---- Pass 1 (load): masked sum + valid count ----
    float acc[2] = {0.f, 0.f};
#pragma unroll
    for (int k = 0; k < KMAX; ++k) {
        const int i = tid + k * THREADS;
        float4 xv = make_float4(0.f, 0.f, 0.f, 0.f);
        int4   mv = make_int4(0, 0, 0, 0);
        if (i < VECS) { xv = xr[i]; mv = mr[i]; }
        const float m0 = mv.x ? 1.f : 0.f;
        const float m1 = mv.y ? 1.f : 0.f;
        const float m2 = mv.z ? 1.f : 0.f;
        const float m3 = mv.w ? 1.f : 0.f;
        mbits |= (mv.x ? 1u : 0u) << (k * 4 + 0);
        mbits |= (mv.y ? 1u : 0u) << (k * 4 + 1);
        mbits |= (mv.z ? 1u : 0u) << (k * 4 + 2);
        mbits |= (mv.w ? 1u : 0u) << (k * 4 + 3);
        v[k][0] = xv.x * m0;
        v[k][1] = xv.y * m1;
        v[k][2] = xv.z * m2;
        v[k][3] = xv.w * m3;
        acc[0] += v[k][0] + v[k][1] + v[k][2] + v[k][3];
        acc[1] += m0 + m1 + m2 + m3;
    }
    block_reduce<2>(acc, sred, tid);
    const float cnt   = acc[1];
    const float inv   = (cnt > 0.f) ? (1.f / cnt) : 0.f;  // nan->0 semantics
    const float mean1 = acc[0] * inv;

    // ---- Pass 2 (registers): order-1 statistics ----
    // st = { sum c^2, sum |c|, sum sign(c), count(c != 0), sum c }
    float st[5] = {0.f, 0.f, 0.f, 0.f, 0.f};
#pragma unroll
    for (int k = 0; k < KMAX; ++k) {
#pragma unroll
        for (int j = 0; j < 4; ++j) {
            const float mk = (mbits >> (k * 4 + j)) & 1u ? 1.f : 0.f;
            const float c  = (v[k][j] - mean1) * mk;   // centered1 (0 where masked)
            const float s  = fsign(c);
            st[0] += c * c;
            st[1] += fabsf(c);
            st[2] += s;
            st[3] += s * s;   // 1 iff c != 0
            st[4] += c;
        }
    }
    block_reduce<5>(st, sred, tid);

    const float var1   = st[0] * inv;
    const float scale1 = sqrtf(var1) * SQRT_2_OVER_PI;

    // Order 2 analytically from order-1 stats:
    //   residual2       = centered1 - scale1*sign(centered1)   (valid entries)
    //   sum(residual2)  = sum(c1) - scale1 * sum(sign)
    //   sum(residual2^2)= sum(c1^2) - 2*scale1*sum|c1| + scale1^2 * Nnz
    const float mean2   = (st[4] - scale1 * st[2]) * inv;
    const float sumr2sq = st[0] - 2.f * scale1 * st[1] + scale1 * scale1 * st[3];
    const float var2    = fmaxf(sumr2sq * inv - mean2 * mean2, 0.f);
    const float scale2  = sqrtf(var2) * SQRT_2_OVER_PI;

    // ---- Pass 3 (write): sum_order = final1 + final2 ----
#pragma unroll
    for (int k = 0; k < KMAX; ++k) {
        const int i = tid + k * THREADS;
        if (i < VECS) {
            float4 o;
            float* op = &o.x;
#pragma unroll
            for (int j = 0; j < 4; ++j) {
                const float mk = (mbits >> (k * 4 + j)) & 1u ? 1.f : 0.f;
                const float c1 = (v[k][j] - mean1) * mk;
                const float s1 = fsign(c1);
                const float r2 = c1 - scale1 * s1;      // residual2 (valid)
                const float c2 = (r2 - mean2) * mk;     // centered2
                const float s2 = fsign(c2);
                op[j] = (mean1 + scale1 * s1 + mean2 + scale2 * s2) * mk;
            }
            outr[i] = o;
        }
    }
}

extern "C" void kernel_launch(void* const* d_in, const int* in_sizes, int n_in,
                              void* d_out, int out_size) {
    const float* x    = (const float*)d_in[0];
    const int*   mask = (const int*)d_in[1];
    float*       out  = (float*)d_out;
    const int oc = out_size / IC;  // 4096
    binarize_kernel<<<oc, THREADS>>>(x, mask, out);
}

// round 5
// speedup vs baseline: 1.2044x; 1.2044x over previous
#include <cuda_runtime.h>

// Binarization_69930657513784: adaptive 2-order residual sign binarization
// x: (4096, 11008) fp32, mask: (4096, 11008) bool stored as INT32
// -> out: (4096, 11008) fp32
//
// One CTA (512 thr) per row; 2 independent CTAs per SM so barrier stalls in
// one CTA overlap with memory streaming in the other. Row cached in registers
// (6 float4 per thread); mask as 24 packed bits. Order-2 stats derived
// analytically; var1 from raw moments so pass 1 needs one reduction of 3.

constexpr int IC      = 11008;
constexpr int VECS    = IC / 4;                         // 2752
constexpr int THREADS = 512;
constexpr int KMAX    = (VECS + THREADS - 1) / THREADS; // 6 (last iter partial)
constexpr int NWARPS  = THREADS / 32;                   // 16
#define SQRT_2_OVER_PI 0.7978845608028654f

__device__ __forceinline__ float fsign(float c) {
    return (c > 0.0f) ? 1.0f : ((c < 0.0f) ? -1.0f : 0.0f);
}

// Block-wide sum reduction of N values across 16 warps.
template <int N, bool FINAL>
__device__ __forceinline__ void block_reduce(float (&vals)[N], float* sred, int tid) {
    const int lane = tid & 31;
    const int warp = tid >> 5;
#pragma unroll
    for (int n = 0; n < N; ++n) {
#pragma unroll
        for (int o = 16; o > 0; o >>= 1)
            vals[n] += __shfl_xor_sync(0xffffffffu, vals[n], o);
    }
    if (lane == 0) {
#pragma unroll
        for (int n = 0; n < N; ++n) sred[warp * N + n] = vals[n];
    }
    __syncthreads();
    if (warp == 0) {
#pragma unroll
        for (int n = 0; n < N; ++n)
            vals[n] = (lane < NWARPS) ? sred[lane * N + n] : 0.f;
#pragma unroll
        for (int n = 0; n < N; ++n) {
#pragma unroll
            for (int o = NWARPS / 2; o > 0; o >>= 1)
                vals[n] += __shfl_xor_sync(0xffffffffu, vals[n], o);
        }
        if (lane == 0) {
#pragma unroll
            for (int n = 0; n < N; ++n) sred[n] = vals[n];
        }
    }
    __syncthreads();
#pragma unroll
    for (int n = 0; n < N; ++n) vals[n] = sred[n];
    if (!FINAL) __syncthreads();  // protect sred for reuse
}

__global__ __launch_bounds__(THREADS, 2)
void binarize_kernel(const float* __restrict__ x,
                     const int* __restrict__ mask,
                     float* __restrict__ out)
{
    __shared__ float sred[NWARPS * 3];
    const int tid  = threadIdx.x;
    const size_t base = (size_t)blockIdx.x * IC;
    const float4* xr   = reinterpret_cast<const float4*>(x + base);
    const int4*   mr   = reinterpret_cast<const int4*>(mask + base);
    float4*       outr = reinterpret_cast<float4*>(out + base);

    // Register-cached row slice: masked values + packed mask bits.
    float        v[KMAX][4];
    unsigned int mbits = 0;   // bit (k*4+j) = mask of element (k, j)

    // ---- Pass 1 (load): Σv, cnt, Σv² ----
    float acc[3] = {0.f, 0.f, 0.f};
#pragma unroll
    for (int k = 0; k < KMAX; ++k) {
        const int i = tid + k * THREADS;
        float4 xv = make_float4(0.f, 0.f, 0.f, 0.f);
        int4   mv = make_int4(0, 0, 0, 0);
        if (i < VECS) { xv = __ldcs(&xr[i]); mv = __ldcs(&mr[i]); }
        const float m0 = mv.x ? 1.f : 0.f;
        const float m1 = mv.y ? 1.f : 0.f;
        const float m2 = mv.z ? 1.f : 0.f;
        const float m3 = mv.w ? 1.f : 0.f;
        mbits |= (mv.x ? 1u : 0u) << (k * 4 + 0);
        mbits |= (mv.y ? 1u : 0u) << (k * 4 + 1);
        mbits |= (mv.z ? 1u : 0u) << (k * 4 + 2);
        mbits |= (mv.w ? 1u : 0u) << (k * 4 + 3);
        v[k][0] = xv.x * m0;
        v[k][1] = xv.y * m1;
        v[k][2] = xv.z * m2;
        v[k][3] = xv.w * m3;
#pragma unroll
        for (int j = 0; j < 4; ++j) {
            acc[0] += v[k][j];
            acc[2] = fmaf(v[k][j], v[k][j], acc[2]);
        }
        acc[1] += m0 + m1 + m2 + m3;
    }
    block_reduce<3, false>(acc, sred, tid);
    const float cnt   = acc[1];
    const float inv   = (cnt > 0.f) ? (1.f / cnt) : 0.f;  // nan->0 semantics
    const float mean1 = acc[0] * inv;
    // Σc1 and Σc1² from raw moments (x masked -> c = (v-mean1)*m):
    const float sumc1   = acc[0] - mean1 * cnt;           // ≈ 0
    const float sumc1sq = acc[2] - mean1 * mean1 * cnt;   // Σv² - mean²·cnt
    const float var1    = sumc1sq * inv;
    const float scale1  = sqrtf(fmaxf(var1, 0.f)) * SQRT_2_OVER_PI;

    // ---- Pass 2 (registers): sign-dependent stats { Σ|c1|, Σsign(c1), Nnz } ----
    float st[3] = {0.f, 0.f, 0.f};
#pragma unroll
    for (int k = 0; k < KMAX; ++k) {
#pragma unroll
        for (int j = 0; j < 4; ++j) {
            const float mk = (mbits >> (k * 4 + j)) & 1u ? 1.f : 0.f;
            const float c  = (v[k][j] - mean1) * mk;   // centered1 (0 where masked)
            const float s  = fsign(c);
            st[0] += fabsf(c);
            st[1] += s;
            st[2] += s * s;   // 1 iff c != 0
        }
    }
    block_reduce<3, true>(st, sred, tid);

    // Order 2 analytically from order-1 stats:
    //   residual2        = centered1 - scale1*sign(centered1)   (valid entries)
    //   sum(residual2)   = Σc1 - scale1 * Σsign
    //   sum(residual2^2) = Σc1² - 2*scale1*Σ|c1| + scale1² * Nnz
    const float mean2   = (sumc1 - scale1 * st[1]) * inv;
    const float sumr2sq = sumc1sq - 2.f * scale1 * st[0] + scale1 * scale1 * st[2];
    const float var2    = fmaxf(sumr2sq * inv - mean2 * mean2, 0.f);
    const float scale2  = sqrtf(var2) * SQRT_2_OVER_PI;

    // ---- Pass 3 (write): sum_order = final1 + final2 ----
#pragma unroll
    for (int k = 0; k < KMAX; ++k) {
        const int i = tid + k * THREADS;
        if (i < VECS) {
            float4 o;
            float* op = &o.x;
#pragma unroll
            for (int j = 0; j < 4; ++j) {
                const float mk = (mbits >> (k * 4 + j)) & 1u ? 1.f : 0.f;
                const float c1 = (v[k][j] - mean1) * mk;
                const float s1 = fsign(c1);
                const float r2 = c1 - scale1 * s1;      // residual2 (valid)
                const float c2 = (r2 - mean2) * mk;     // centered2
                const float s2 = fsign(c2);
                op[j] = (mean1 + scale1 * s1 + mean2 + scale2 * s2) * mk;
            }
            __stcs(&outr[i], o);
        }
    }
}

extern "C" void kernel_launch(void* const* d_in, const int* in_sizes, int n_in,
                              void* d_out, int out_size) {
    const float* x    = (const float*)d_in[0];
    const int*   mask = (const int*)d_in[1];
    float*       out  = (float*)d_out;
    const int oc = out_size / IC;  // 4096
    binarize_kernel<<<oc, THREADS>>>(x, mask, out);
}

// round 7
// speedup vs baseline: 1.2428x; 1.0318x over previous
#include <cuda_runtime.h>

// Binarization_69930657513784: adaptive 2-order residual sign binarization
// x: (4096, 11008) fp32, mask: bool stored as INT32 -> out fp32.
//
// Persistent kernel: 296 CTAs (2/SM on 148 SMs), each grid-strides over rows.
// No wave re-synchronization -> co-resident CTAs drift out of phase, so one
// CTA's reductions/compute overlap the other's HBM streaming. Row cached in
// registers (6 float4/thread); mask as 24 packed bits; valid count via popc;
// centered values cached in-place so the epilogue does no recompute.

constexpr int IC      = 11008;
constexpr int VECS    = IC / 4;                         // 2752
constexpr int THREADS = 512;
constexpr int KMAX    = (VECS + THREADS - 1) / THREADS; // 6 (last iter partial)
constexpr int NWARPS  = THREADS / 32;                   // 16
constexpr int GRID    = 296;                            // 2 CTAs x 148 SMs
#define SQRT_2_OVER_PI 0.7978845608028654f

__device__ __forceinline__ float fsign(float c) {
    return (c > 0.0f) ? 1.0f : ((c < 0.0f) ? -1.0f : 0.0f);
}

// Block-wide sum reduction of N values across 16 warps.
template <int N, bool FINAL>
__device__ __forceinline__ void block_reduce(float (&vals)[N], float* sred, int tid) {
    const int lane = tid & 31;
    const int warp = tid >> 5;
#pragma unroll
    for (int n = 0; n < N; ++n) {
#pragma unroll
        for (int o = 16; o > 0; o >>= 1)
            vals[n] += __shfl_xor_sync(0xffffffffu, vals[n], o);
    }
    if (lane == 0) {
#pragma unroll
        for (int n = 0; n < N; ++n) sred[warp * N + n] = vals[n];
    }
    __syncthreads();
    if (warp == 0) {
#pragma unroll
        for (int n = 0; n < N; ++n)
            vals[n] = (lane < NWARPS) ? sred[lane * N + n] : 0.f;
#pragma unroll
        for (int n = 0; n < N; ++n) {
#pragma unroll
            for (int o = NWARPS / 2; o > 0; o >>= 1)
                vals[n] += __shfl_xor_sync(0xffffffffu, vals[n], o);
        }
        if (lane == 0) {
#pragma unroll
            for (int n = 0; n < N; ++n) sred[n] = vals[n];
        }
    }
    __syncthreads();
#pragma unroll
    for (int n = 0; n < N; ++n) vals[n] = sred[n];
    if (!FINAL) __syncthreads();  // protect sred before next reduction reuses it
}

__global__ __launch_bounds__(THREADS, 2)
void binarize_kernel(const float* __restrict__ x,
                     const int* __restrict__ mask,
                     float* __restrict__ out,
                     int oc)
{
    __shared__ float sred[NWARPS * 3];
    const int tid = threadIdx.x;

    for (int row = blockIdx.x; row < oc; row += GRID) {
        const size_t base = (size_t)row * IC;
        const float4* xr   = reinterpret_cast<const float4*>(x + base);
        const int4*   mr   = reinterpret_cast<const int4*>(mask + base);
        float4*       outr = reinterpret_cast<float4*>(out + base);

        // Register-cached row slice + packed mask bits.
        float        v[KMAX][4];
        unsigned int mbits = 0;   // bit (k*4+j) = mask of element (k, j)

        // ---- Pass 1 (load): Σv, Σv² ; count via popc ----
        float acc[3] = {0.f, 0.f, 0.f};
#pragma unroll
        for (int k = 0; k < KMAX; ++k) {
            const int i = tid + k * THREADS;
            float4 xv = make_float4(0.f, 0.f, 0.f, 0.f);
            int4   mv = make_int4(0, 0, 0, 0);
            if (i < VECS) { xv = __ldcs(&xr[i]); mv = __ldcs(&mr[i]); }
            mbits |= (mv.x ? 1u : 0u) << (k * 4 + 0);
            mbits |= (mv.y ? 1u : 0u) << (k * 4 + 1);
            mbits |= (mv.z ? 1u : 0u) << (k * 4 + 2);
            mbits |= (mv.w ? 1u : 0u) << (k * 4 + 3);
            v[k][0] = mv.x ? xv.x : 0.f;
            v[k][1] = mv.y ? xv.y : 0.f;
            v[k][2] = mv.z ? xv.z : 0.f;
            v[k][3] = mv.w ? xv.w : 0.f;
#pragma unroll
            for (int j = 0; j < 4; ++j) {
                acc[0] += v[k][j];
                acc[1] = fmaf(v[k][j], v[k][j], acc[1]);
            }
        }
        acc[2] = (float)__popc(mbits);   // valid count (thread-local)
        block_reduce<3, false>(acc, sred, tid);

        const float cnt   = acc[2];
        const float inv   = (cnt > 0.f) ? (1.f / cnt) : 0.f;  // nan->0 semantics
        const float mean1 = acc[0] * inv;
        // Raw-moment identities on valid entries:
        const float sumc1   = acc[0] - mean1 * cnt;           // Σc1 (≈0)
        const float sumc1sq = acc[1] - mean1 * mean1 * cnt;   // Σc1²
        const float scale1  = sqrtf(fmaxf(sumc1sq * inv, 0.f)) * SQRT_2_OVER_PI;

        // ---- Pass 2 (registers): center in place, sign stats ----
        // st = { Σ|c1|, Σsign(c1), Nnz(c1) }
        float st[3] = {0.f, 0.f, 0.f};
#pragma unroll
        for (int k = 0; k < KMAX; ++k) {
#pragma unroll
            for (int j = 0; j < 4; ++j) {
                const bool  mk = (mbits >> (k * 4 + j)) & 1u;
                const float c  = mk ? (v[k][j] - mean1) : 0.f;
                v[k][j] = c;                       // cache centered1 for pass 3
                const float s = fsign(c);
                st[0] = fmaf(c, s, st[0]);         // |c|
                st[1] += s;
                st[2] += s * s;                    // 1 iff c != 0
            }
        }
        block_reduce<3, true>(st, sred, tid);

        // Order-2 stats analytically:
        //   residual2        = c1 - scale1*sign(c1)           (valid entries)
        //   Σr2  = Σc1 - scale1·Σsign ; Σr2² = Σc1² - 2·scale1·Σ|c1| + scale1²·Nnz
        const float mean2   = (sumc1 - scale1 * st[1]) * inv;
        const float sumr2sq = sumc1sq - 2.f * scale1 * st[0] + scale1 * scale1 * st[2];
        const float var2    = fmaxf(sumr2sq * inv - mean2 * mean2, 0.f);
        const float scale2  = sqrtf(var2) * SQRT_2_OVER_PI;
        const float mean12  = mean1 + mean2;

        // ---- Pass 3 (write): sum_order = final1 + final2 ----
#pragma unroll
        for (int k = 0; k < KMAX; ++k) {
            const int i = tid + k * THREADS;
            if (i < VECS) {
                float4 o;
                float* op = &o.x;
#pragma unroll
                for (int j = 0; j < 4; ++j) {
                    const bool  mk = (mbits >> (k * 4 + j)) & 1u;
                    const float c1 = v[k][j];                 // centered1
                    const float s1 = fsign(c1);
                    const float c2 = fmaf(-scale1, s1, c1) - mean2;  // centered2 (valid)
                    const float s2 = fsign(c2);
                    const float r  = fmaf(scale2, s2, fmaf(scale1, s1, mean12));
                    op[j] = mk ? r : 0.f;
                }
                __stcs(&outr[i], o);
            }
        }
        // Required: block_reduce<3,true> skips its trailing sync, so without
        // this barrier a fast thread could re-enter block_reduce next row and
        // overwrite sred[] while a slow thread still reads the broadcast.
        __syncthreads();
    }
}

extern "C" void kernel_launch(void* const* d_in, const int* in_sizes, int n_in,
                              void* d_out, int out_size) {
    const float* x    = (const float*)d_in[0];
    const int*   mask = (const int*)d_in[1];
    float*       out  = (float*)d_out;
    const int oc = out_size / IC;  // 4096
    binarize_kernel<<<GRID, THREADS>>>(x, mask, out, oc);
}